// round 1
// baseline (speedup 1.0000x reference)
#include <cuda_runtime.h>
#include <cuda_bf16.h>
#include <cstdint>

// Problem constants (fixed by the dataset)
#define NN   8192   // graph nodes
#define GG   128    // input features  (== F)
#define FF   128    // output features
#define KT   4      // filter taps
#define BN   64     // GEMM N-tile per CTA
#define BK   64     // GEMM K-chunk
#define NCH  (NN / BK)

// Scratch (device globals: allocation-free per harness rules)
__device__ float g_P[4 * FF * NN];   // P_k = W_k x^T, 16 MB
__device__ float g_v[2 * FF * NN];   // Horner ping-pong, 8 MB

// ---------------------------------------------------------------------------
// prep: P[k][f][n] = sum_g weight[f,0,k,g] * x[n,g]
// ---------------------------------------------------------------------------
__global__ __launch_bounds__(256) void prep_kernel(
    const float* __restrict__ x,   // [NN, GG]
    const float* __restrict__ w,   // [FF, KT, GG] (E=1 folded)
    float* __restrict__ P)         // [4][FF][NN]
{
    __shared__ float xs[64][129];
    __shared__ float ws[4][512];
    const int tid = threadIdx.x;
    const int n0 = blockIdx.x * 64;

    for (int i = tid; i < 64 * 128; i += 256) {
        int n = i >> 7, g = i & 127;
        xs[n][g] = x[(n0 + n) * GG + g];
    }
    const int nloc = tid & 63;
    const int fsel = tid >> 6;

    for (int fi = 0; fi < 32; ++fi) {
        __syncthreads();
        for (int i = tid; i < 2048; i += 256) {
            int j = i >> 9, idx = i & 511;
            ws[j][idx] = w[(fi * 4 + j) * 512 + idx];
        }
        __syncthreads();
        float a0 = 0.f, a1 = 0.f, a2 = 0.f, a3 = 0.f;
        #pragma unroll 8
        for (int g = 0; g < 128; ++g) {
            float xv = xs[nloc][g];
            a0 += ws[fsel][g]        * xv;
            a1 += ws[fsel][128 + g]  * xv;
            a2 += ws[fsel][256 + g]  * xv;
            a3 += ws[fsel][384 + g]  * xv;
        }
        const int f = fi * 4 + fsel;
        P[(0 * FF + f) * NN + n0 + nloc] = a0;
        P[(1 * FF + f) * NN + n0 + nloc] = a1;
        P[(2 * FF + f) * NN + n0 + nloc] = a2;
        P[(3 * FF + f) * NN + n0 + nloc] = a3;
    }
}

// ---------------------------------------------------------------------------
// GEMM step: Out = V @ S + Padd (+ bias), with bf16 split-precision MMA
// ---------------------------------------------------------------------------

#define LDSM4(R0, R1, R2, R3, ADDR)                                          \
    asm volatile("ldmatrix.sync.aligned.m8n8.x4.shared.b16 {%0,%1,%2,%3}, [%4];" \
                 : "=r"(R0), "=r"(R1), "=r"(R2), "=r"(R3) : "r"(ADDR))

#define LDSM4T(R0, R1, R2, R3, ADDR)                                         \
    asm volatile("ldmatrix.sync.aligned.m8n8.x4.trans.shared.b16 {%0,%1,%2,%3}, [%4];" \
                 : "=r"(R0), "=r"(R1), "=r"(R2), "=r"(R3) : "r"(ADDR))

#define MMA_BF16(C, A, B0, B1)                                               \
    asm volatile("mma.sync.aligned.m16n8k16.row.col.f32.bf16.bf16.f32 "      \
                 "{%0,%1,%2,%3}, {%4,%5,%6,%7}, {%8,%9}, {%0,%1,%2,%3};"     \
                 : "+f"((C)[0]), "+f"((C)[1]), "+f"((C)[2]), "+f"((C)[3])    \
                 : "r"((A)[0]), "r"((A)[1]), "r"((A)[2]), "r"((A)[3]),       \
                   "r"(B0), "r"(B1))

// Split fp32x4 into bf16 hi/lo pairs and store 8B each to shared.
__device__ __forceinline__ void cvt_split_store(unsigned haddr, unsigned laddr, float4 v)
{
    __nv_bfloat162 h01 = __floats2bfloat162_rn(v.x, v.y);
    __nv_bfloat162 h23 = __floats2bfloat162_rn(v.z, v.w);
    unsigned uh01 = *reinterpret_cast<unsigned*>(&h01);
    unsigned uh23 = *reinterpret_cast<unsigned*>(&h23);
    float hx = __uint_as_float(uh01 << 16);
    float hy = __uint_as_float(uh01 & 0xFFFF0000u);
    float hz = __uint_as_float(uh23 << 16);
    float hw = __uint_as_float(uh23 & 0xFFFF0000u);
    __nv_bfloat162 l01 = __floats2bfloat162_rn(v.x - hx, v.y - hy);
    __nv_bfloat162 l23 = __floats2bfloat162_rn(v.z - hz, v.w - hw);
    unsigned ul01 = *reinterpret_cast<unsigned*>(&l01);
    unsigned ul23 = *reinterpret_cast<unsigned*>(&l23);
    asm volatile("st.shared.v2.u32 [%0], {%1, %2};" :: "r"(haddr), "r"(uh01), "r"(uh23));
    asm volatile("st.shared.v2.u32 [%0], {%1, %2};" :: "r"(laddr), "r"(ul01), "r"(ul23));
}

__global__ __launch_bounds__(256) void gemm_step(
    const float* __restrict__ V,     // [FF, NN]
    const float* __restrict__ S,     // [NN, NN]
    const float* __restrict__ Padd,  // [FF, NN]
    const float* __restrict__ bias,  // [FF] or nullptr
    float* __restrict__ Out)         // [FF, NN]
{
    __shared__ __align__(1024) unsigned char smem[49152];
    // regions: Ah[128m][64k] (16K), Al (16K), Bh[64k][64n] (8K), Bl (8K)
    const unsigned AH = 0, AL = 16384, BH = 32768, BL = 40960;

    const int tid  = threadIdx.x;
    const int lane = tid & 31;
    const int wid  = tid >> 5;
    const int n0   = blockIdx.x * BN;

    unsigned sb;
    asm("{ .reg .u64 t; cvta.to.shared.u64 t, %1; cvt.u32.u64 %0, t; }"
        : "=r"(sb) : "l"(smem));

    float4 pa[8];  // prefetched A (V) chunk: 128x64 fp32 / 256 thr
    float4 pb[4];  // prefetched B (S) chunk: 64x64  fp32 / 256 thr

    float acc[2][4][4];
    #pragma unroll
    for (int a = 0; a < 2; ++a)
        #pragma unroll
        for (int b = 0; b < 4; ++b)
            #pragma unroll
            for (int c = 0; c < 4; ++c) acc[a][b][c] = 0.f;

    const int wm = (wid & 3) * 32;   // warp M offset (4 warp-rows x 32)
    const int wn = (wid >> 2) * 32;  // warp N offset (2 warp-cols x 32)

    // prologue: load chunk 0
    #pragma unroll
    for (int i = 0; i < 8; ++i) {
        int idx = tid + i * 256, m = idx >> 4, k4 = idx & 15;
        pa[i] = *reinterpret_cast<const float4*>(V + m * NN + k4 * 4);
    }
    #pragma unroll
    for (int i = 0; i < 4; ++i) {
        int idx = tid + i * 256, k = idx >> 4, n4 = idx & 15;
        pb[i] = *reinterpret_cast<const float4*>(S + (size_t)k * NN + n0 + n4 * 4);
    }

    for (int c = 0; c < NCH; ++c) {
        __syncthreads();  // previous compute done; smem free

        // convert + stash chunk c
        #pragma unroll
        for (int i = 0; i < 8; ++i) {
            int idx = tid + i * 256, m = idx >> 4, k4 = idx & 15;
            unsigned off = (unsigned)(m * 128 + ((k4 * 8) ^ ((m & 7) << 4)));
            cvt_split_store(sb + AH + off, sb + AL + off, pa[i]);
        }
        #pragma unroll
        for (int i = 0; i < 4; ++i) {
            int idx = tid + i * 256, k = idx >> 4, n4 = idx & 15;
            unsigned off = (unsigned)(k * 128 + ((n4 * 8) ^ ((k & 7) << 4)));
            cvt_split_store(sb + BH + off, sb + BL + off, pb[i]);
        }

        // prefetch chunk c+1 (latency hidden by compute below)
        if (c + 1 < NCH) {
            int cb = (c + 1) * BK;
            #pragma unroll
            for (int i = 0; i < 8; ++i) {
                int idx = tid + i * 256, m = idx >> 4, k4 = idx & 15;
                pa[i] = *reinterpret_cast<const float4*>(V + m * NN + cb + k4 * 4);
            }
            #pragma unroll
            for (int i = 0; i < 4; ++i) {
                int idx = tid + i * 256, k = idx >> 4, n4 = idx & 15;
                pb[i] = *reinterpret_cast<const float4*>(S + (size_t)(cb + k) * NN + n0 + n4 * 4);
            }
        }

        __syncthreads();  // smem chunk c ready

        // compute: 4 k16 steps, 3 split products each
        #pragma unroll
        for (int kk = 0; kk < 4; ++kk) {
            unsigned ah[2][4], al[2][4], bh[4][2], bl[4][2];
            #pragma unroll
            for (int mi = 0; mi < 2; ++mi) {
                int m = wm + mi * 16 + (lane & 15);
                unsigned koff = (unsigned)((kk * 16 + ((lane >> 4) << 3)) * 2);
                unsigned off = (unsigned)(m * 128) + (koff ^ (unsigned)((m & 7) << 4));
                LDSM4(ah[mi][0], ah[mi][1], ah[mi][2], ah[mi][3], sb + AH + off);
                LDSM4(al[mi][0], al[mi][1], al[mi][2], al[mi][3], sb + AL + off);
            }
            #pragma unroll
            for (int ni = 0; ni < 2; ++ni) {
                int k = kk * 16 + (lane & 15);
                int n = wn + ni * 16 + ((lane >> 4) << 3);
                unsigned off = (unsigned)(k * 128) + (((unsigned)(n * 2)) ^ (unsigned)((k & 7) << 4));
                unsigned t0, t1, t2, t3;
                LDSM4T(t0, t1, t2, t3, sb + BH + off);
                bh[ni * 2][0] = t0; bh[ni * 2][1] = t1;
                bh[ni * 2 + 1][0] = t2; bh[ni * 2 + 1][1] = t3;
                LDSM4T(t0, t1, t2, t3, sb + BL + off);
                bl[ni * 2][0] = t0; bl[ni * 2][1] = t1;
                bl[ni * 2 + 1][0] = t2; bl[ni * 2 + 1][1] = t3;
            }
            #pragma unroll
            for (int mi = 0; mi < 2; ++mi)
                #pragma unroll
                for (int j = 0; j < 4; ++j) {
                    MMA_BF16(acc[mi][j], ah[mi], bh[j][0], bh[j][1]);  // hi*hi
                    MMA_BF16(acc[mi][j], ah[mi], bl[j][0], bl[j][1]);  // hi*lo
                    MMA_BF16(acc[mi][j], al[mi], bh[j][0], bh[j][1]);  // lo*hi
                }
        }
    }

    // epilogue: Out = acc + Padd (+ bias)
    const int r  = lane >> 2;
    const int c2 = (lane & 3) * 2;
    #pragma unroll
    for (int mi = 0; mi < 2; ++mi) {
        const int m0 = wm + mi * 16 + r;
        float bv0 = 0.f, bv1 = 0.f;
        if (bias != nullptr) { bv0 = bias[m0]; bv1 = bias[m0 + 8]; }
        #pragma unroll
        for (int j = 0; j < 4; ++j) {
            const int n = n0 + wn + j * 8 + c2;
            float2 p0 = *reinterpret_cast<const float2*>(Padd + m0 * NN + n);
            float2 p8 = *reinterpret_cast<const float2*>(Padd + (m0 + 8) * NN + n);
            float2 o0, o8;
            o0.x = acc[mi][j][0] + p0.x + bv0;
            o0.y = acc[mi][j][1] + p0.y + bv0;
            o8.x = acc[mi][j][2] + p8.x + bv1;
            o8.y = acc[mi][j][3] + p8.y + bv1;
            *reinterpret_cast<float2*>(Out + m0 * NN + n)       = o0;
            *reinterpret_cast<float2*>(Out + (m0 + 8) * NN + n) = o8;
        }
    }
}

// ---------------------------------------------------------------------------
// launch: prep, then 3 Horner GEMMs  y = ((P3 S + P2) S + P1) S + P0 + b
// ---------------------------------------------------------------------------
extern "C" void kernel_launch(void* const* d_in, const int* in_sizes, int n_in,
                              void* d_out, int out_size)
{
    (void)in_sizes; (void)n_in; (void)out_size;
    const float* x    = (const float*)d_in[0];  // [8192,128]
    const float* S    = (const float*)d_in[1];  // [1,8192,8192]
    const float* w    = (const float*)d_in[2];  // [128,1,4,128]
    const float* bias = (const float*)d_in[3];  // [128,1]
    float* out = (float*)d_out;                 // [1,128,8192]

    float *P, *v;
    cudaGetSymbolAddress((void**)&P, g_P);
    cudaGetSymbolAddress((void**)&v, g_v);
    float* P0 = P;
    float* P1 = P + (size_t)FF * NN;
    float* P2 = P + (size_t)2 * FF * NN;
    float* P3 = P + (size_t)3 * FF * NN;
    float* v0 = v;
    float* v1 = v + (size_t)FF * NN;

    prep_kernel<<<NN / 64, 256>>>(x, w, P);
    gemm_step<<<NN / BN, 256>>>(P3, S, P2, nullptr, v0);
    gemm_step<<<NN / BN, 256>>>(v0, S, P1, nullptr, v1);
    gemm_step<<<NN / BN, 256>>>(v1, S, P0, bias, out);
}

// round 3
// speedup vs baseline: 1.0325x; 1.0325x over previous
#include <cuda_runtime.h>
#include <cuda_bf16.h>
#include <cstdint>

// Problem constants
#define NN   8192
#define FF   128
#define BN   64      // output-column tile per CTA
#define BK   64      // K chunk
#define NCH  (NN / BK)
#define NSTAGE 3

// Scratch
__device__ float g_P[4 * FF * NN];   // P_k = W_k x^T
__device__ float g_v[2 * FF * NN];   // Horner ping-pong

// ---------------------------------------------------------------------------
// helpers
// ---------------------------------------------------------------------------
__device__ __forceinline__ uint32_t smem_u32(const void* p) {
    uint32_t a;
    asm("{ .reg .u64 t; cvta.to.shared.u64 t, %1; cvt.u32.u64 %0, t; }"
        : "=r"(a) : "l"(p));
    return a;
}

#define MBARRIER_INIT(addr, cnt) \
    asm volatile("mbarrier.init.shared.b64 [%0], %1;" :: "r"(addr), "r"(cnt) : "memory")
#define MBARRIER_ARRIVE(addr) \
    asm volatile("mbarrier.arrive.shared.b64 _, [%0];" :: "r"(addr) : "memory")
#define MBARRIER_WAIT(addr, ph) do {                                          \
    uint32_t _m = (addr), _p = (ph), _d;                                      \
    asm volatile("{\n\t.reg .pred p;\n\t"                                     \
        "mbarrier.try_wait.parity.acquire.cta.shared::cta.b64 p, [%1], %2;\n\t" \
        "selp.b32 %0, 1, 0, p;\n\t}" : "=r"(_d) : "r"(_m), "r"(_p) : "memory"); \
    if (!_d) {                                                                \
        asm volatile("{\n\t.reg .pred P1;\n\t"                                \
            "WL_%=:\n\t"                                                      \
            "mbarrier.try_wait.parity.acquire.cta.shared::cta.b64 P1, [%0], %1, 0x989680;\n\t" \
            "@P1 bra.uni WD_%=;\n\t"                                          \
            "bra.uni WL_%=;\n\t"                                              \
            "WD_%=:\n\t}" :: "r"(_m), "r"(_p) : "memory");                    \
    }                                                                         \
} while (0)

#define LDSM4(R0, R1, R2, R3, ADDR)                                          \
    asm volatile("ldmatrix.sync.aligned.m8n8.x4.shared.b16 {%0,%1,%2,%3}, [%4];" \
                 : "=r"(R0), "=r"(R1), "=r"(R2), "=r"(R3) : "r"(ADDR))
#define LDSM4T(R0, R1, R2, R3, ADDR)                                         \
    asm volatile("ldmatrix.sync.aligned.m8n8.x4.trans.shared.b16 {%0,%1,%2,%3}, [%4];" \
                 : "=r"(R0), "=r"(R1), "=r"(R2), "=r"(R3) : "r"(ADDR))
#define MMA_BF16(C, A, B0, B1)                                               \
    asm volatile("mma.sync.aligned.m16n8k16.row.col.f32.bf16.bf16.f32 "      \
                 "{%0,%1,%2,%3}, {%4,%5,%6,%7}, {%8,%9}, {%0,%1,%2,%3};"     \
                 : "+f"((C)[0]), "+f"((C)[1]), "+f"((C)[2]), "+f"((C)[3])    \
                 : "r"((A)[0]), "r"((A)[1]), "r"((A)[2]), "r"((A)[3]),       \
                   "r"(B0), "r"(B1))

// swizzled byte offset within a tile of 128B rows
__device__ __forceinline__ uint32_t swz(int row, int byte_in_row) {
    return (uint32_t)(row * 128 + (byte_in_row ^ ((row & 7) << 4)));
}

// split float4 -> bf16x2 hi pair + lo pair (proven in round 1)
__device__ __forceinline__ void split4(float4 v, uint32_t& h01, uint32_t& h23,
                                       uint32_t& l01, uint32_t& l23) {
    __nv_bfloat162 a = __floats2bfloat162_rn(v.x, v.y);
    __nv_bfloat162 b = __floats2bfloat162_rn(v.z, v.w);
    h01 = *reinterpret_cast<uint32_t*>(&a);
    h23 = *reinterpret_cast<uint32_t*>(&b);
    float hx = __uint_as_float(h01 << 16);
    float hy = __uint_as_float(h01 & 0xFFFF0000u);
    float hz = __uint_as_float(h23 << 16);
    float hw = __uint_as_float(h23 & 0xFFFF0000u);
    __nv_bfloat162 c = __floats2bfloat162_rn(v.x - hx, v.y - hy);
    __nv_bfloat162 d = __floats2bfloat162_rn(v.z - hz, v.w - hw);
    l01 = *reinterpret_cast<uint32_t*>(&c);
    l23 = *reinterpret_cast<uint32_t*>(&d);
}
__device__ __forceinline__ void sts_v2(uint32_t addr, uint32_t a, uint32_t b) {
    asm volatile("st.shared.v2.u32 [%0], {%1, %2};" :: "r"(addr), "r"(a), "r"(b));
}

// ---------------------------------------------------------------------------
// SMEM layout: [0,1024) barriers, then NSTAGE x 48KB stages
//   stage: Ah(16K) | Al(16K) | Bh(8K) | Bl(8K)
// ---------------------------------------------------------------------------
#define ST_BASE(s)  (1024 + (s) * 49152)
#define OFF_AH      0
#define OFF_AL      16384
#define OFF_BH      32768
#define OFF_BL      40960
#define BAR_FULL(s) (16 + (s) * 16)
#define BAR_EMP(s)  (16 + (s) * 16 + 8)
#define GEMM_SMEM   (1024 + NSTAGE * 49152)

// ---------------------------------------------------------------------------
// GEMM: Out[128, NN] = V[128, NN] @ S[NN, NN] + Padd (+ bias)
// 384 threads: warps 0-7 compute (ldmatrix+MMA), warps 8-11 produce.
// ---------------------------------------------------------------------------
__global__ __launch_bounds__(384, 1) void gemm_ws(
    const float* __restrict__ V, const float* __restrict__ S,
    const float* __restrict__ Padd, const float* __restrict__ bias,
    float* __restrict__ Out)
{
    extern __shared__ __align__(1024) char smem[];
    const uint32_t sb = smem_u32(smem);
    const int tid  = threadIdx.x;
    const int wid  = tid >> 5;
    const int lane = tid & 31;
    const int n0   = blockIdx.x * BN;

    if (tid == 0) {
        #pragma unroll
        for (int s = 0; s < NSTAGE; ++s) {
            MBARRIER_INIT(sb + BAR_FULL(s), 128);  // 128 producer threads
            MBARRIER_INIT(sb + BAR_EMP(s), 256);   // 256 compute threads
        }
    }
    __syncthreads();

    if (wid >= 8) {
        // ---------------- producers (128 threads) ----------------
        const int t = tid - 256;
        float4 ra[16];   // A: V tile 128m x 64k fp32
        float4 rb[8];    // B: S tile 64k x 64n fp32
        #pragma unroll
        for (int j = 0; j < 16; ++j) {
            int idx = t + 128 * j, m = idx >> 4, k4 = idx & 15;
            ra[j] = *reinterpret_cast<const float4*>(V + (size_t)m * NN + k4 * 4);
        }
        #pragma unroll
        for (int j = 0; j < 8; ++j) {
            int idx = t + 128 * j, k = idx >> 4, n4 = idx & 15;
            rb[j] = *reinterpret_cast<const float4*>(S + (size_t)k * NN + n0 + n4 * 4);
        }
        int st = 0, ph = 1;
        for (int c = 0; c < NCH; ++c) {
            MBARRIER_WAIT(sb + BAR_EMP(st), ph);
            const uint32_t base = sb + ST_BASE(st);
            #pragma unroll
            for (int j = 0; j < 16; ++j) {
                int idx = t + 128 * j, m = idx >> 4, k4 = idx & 15;
                uint32_t h0, h1, l0, l1;
                split4(ra[j], h0, h1, l0, l1);
                uint32_t off = swz(m, k4 * 8);
                sts_v2(base + OFF_AH + off, h0, h1);
                sts_v2(base + OFF_AL + off, l0, l1);
            }
            #pragma unroll
            for (int j = 0; j < 8; ++j) {
                int idx = t + 128 * j, k = idx >> 4, n4 = idx & 15;
                uint32_t h0, h1, l0, l1;
                split4(rb[j], h0, h1, l0, l1);
                uint32_t off = swz(k, n4 * 8);
                sts_v2(base + OFF_BH + off, h0, h1);
                sts_v2(base + OFF_BL + off, l0, l1);
            }
            MBARRIER_ARRIVE(sb + BAR_FULL(st));
            if (++st == NSTAGE) { st = 0; ph ^= 1; }
            if (c + 1 < NCH) {
                const int k0 = (c + 1) * BK;
                #pragma unroll
                for (int j = 0; j < 16; ++j) {
                    int idx = t + 128 * j, m = idx >> 4, k4 = idx & 15;
                    ra[j] = *reinterpret_cast<const float4*>(V + (size_t)m * NN + k0 + k4 * 4);
                }
                #pragma unroll
                for (int j = 0; j < 8; ++j) {
                    int idx = t + 128 * j, k = idx >> 4, n4 = idx & 15;
                    rb[j] = *reinterpret_cast<const float4*>(S + (size_t)(k0 + k) * NN + n0 + n4 * 4);
                }
            }
        }
        return;   // producers exit
    }

    // ---------------- compute warps (256 threads) ----------------
    float acc[2][4][4];
    #pragma unroll
    for (int a = 0; a < 2; ++a)
        #pragma unroll
        for (int b = 0; b < 4; ++b)
            #pragma unroll
            for (int c = 0; c < 4; ++c) acc[a][b][c] = 0.f;

    const int wm = (wid & 3) * 32;
    const int wn = (wid >> 2) * 32;

    int st = 0, ph = 0;
    for (int c = 0; c < NCH; ++c) {
        MBARRIER_WAIT(sb + BAR_FULL(st), ph);
        const uint32_t base = sb + ST_BASE(st);
        #pragma unroll
        for (int kk = 0; kk < 4; ++kk) {
            unsigned ah[2][4], al[2][4], bh[4][2], bl[4][2];
            #pragma unroll
            for (int mi = 0; mi < 2; ++mi) {
                int m = wm + mi * 16 + (lane & 15);
                unsigned koff = (unsigned)((kk * 16 + ((lane >> 4) << 3)) * 2);
                unsigned off = (unsigned)(m * 128) + (koff ^ (unsigned)((m & 7) << 4));
                LDSM4(ah[mi][0], ah[mi][1], ah[mi][2], ah[mi][3], base + OFF_AH + off);
                LDSM4(al[mi][0], al[mi][1], al[mi][2], al[mi][3], base + OFF_AL + off);
            }
            #pragma unroll
            for (int ni = 0; ni < 2; ++ni) {
                int k = kk * 16 + (lane & 15);
                int n = wn + ni * 16 + ((lane >> 4) << 3);
                unsigned off = (unsigned)(k * 128) + (((unsigned)(n * 2)) ^ (unsigned)((k & 7) << 4));
                unsigned t0, t1, t2, t3;
                LDSM4T(t0, t1, t2, t3, base + OFF_BH + off);
                bh[ni * 2][0] = t0; bh[ni * 2][1] = t1;
                bh[ni * 2 + 1][0] = t2; bh[ni * 2 + 1][1] = t3;
                LDSM4T(t0, t1, t2, t3, base + OFF_BL + off);
                bl[ni * 2][0] = t0; bl[ni * 2][1] = t1;
                bl[ni * 2 + 1][0] = t2; bl[ni * 2 + 1][1] = t3;
            }
            #pragma unroll
            for (int mi = 0; mi < 2; ++mi)
                #pragma unroll
                for (int j = 0; j < 4; ++j) {
                    MMA_BF16(acc[mi][j], ah[mi], bh[j][0], bh[j][1]);  // hi*hi
                    MMA_BF16(acc[mi][j], ah[mi], bl[j][0], bl[j][1]);  // hi*lo
                    MMA_BF16(acc[mi][j], al[mi], bh[j][0], bh[j][1]);  // lo*hi
                }
        }
        MBARRIER_ARRIVE(sb + BAR_EMP(st));
        if (++st == NSTAGE) { st = 0; ph ^= 1; }
    }

    // epilogue
    const int r  = lane >> 2;
    const int c2 = (lane & 3) * 2;
    #pragma unroll
    for (int mi = 0; mi < 2; ++mi) {
        const int m0 = wm + mi * 16 + r;
        float bv0 = 0.f, bv1 = 0.f;
        if (bias != nullptr) { bv0 = bias[m0]; bv1 = bias[m0 + 8]; }
        #pragma unroll
        for (int j = 0; j < 4; ++j) {
            const int n = n0 + wn + j * 8 + c2;
            float2 p0 = *reinterpret_cast<const float2*>(Padd + (size_t)m0 * NN + n);
            float2 p8 = *reinterpret_cast<const float2*>(Padd + (size_t)(m0 + 8) * NN + n);
            float2 o0, o8;
            o0.x = acc[mi][j][0] + p0.x + bv0;
            o0.y = acc[mi][j][1] + p0.y + bv0;
            o8.x = acc[mi][j][2] + p8.x + bv1;
            o8.y = acc[mi][j][3] + p8.y + bv1;
            *reinterpret_cast<float2*>(Out + (size_t)m0 * NN + n)       = o0;
            *reinterpret_cast<float2*>(Out + (size_t)(m0 + 8) * NN + n) = o8;
        }
    }
}

// ---------------------------------------------------------------------------
// prep: P[tap][f][n] = sum_g W[f,tap,g] * x[n,g]
// grid = NN/64 CTAs, 256 threads. Register-tiled 4n x 4f rank-1 updates.
// smem: xsT[128g][68 pad] (x transposed), wsT[128g][68 pad] per kf-tile.
// ---------------------------------------------------------------------------
#define XS_STRIDE 68
#define PREP_SMEM (2 * 128 * XS_STRIDE * 4)

__global__ __launch_bounds__(256, 1) void prep_reg(
    const float* __restrict__ x,   // [NN, 128]
    const float* __restrict__ w,   // [128 f, 4 tap, 128 g]
    float* __restrict__ P)         // [4][128][NN]
{
    extern __shared__ __align__(16) float sm[];
    float* xsT = sm;                      // [128][68]
    float* wsT = sm + 128 * XS_STRIDE;    // [128][68]
    const int tid = threadIdx.x;
    const int n0 = blockIdx.x * 64;

    // load + transpose x tile: xsT[g][n] = x[n0+n][g]
    #pragma unroll
    for (int i = 0; i < 8; ++i) {
        int idx = tid + 256 * i;
        int n = idx >> 5, q = idx & 31;
        float4 v = *reinterpret_cast<const float4*>(x + (size_t)(n0 + n) * 128 + q * 4);
        xsT[(4 * q + 0) * XS_STRIDE + n] = v.x;
        xsT[(4 * q + 1) * XS_STRIDE + n] = v.y;
        xsT[(4 * q + 2) * XS_STRIDE + n] = v.z;
        xsT[(4 * q + 3) * XS_STRIDE + n] = v.w;
    }

    const int ni = (tid & 15) * 4;
    const int fj = (tid >> 4) * 4;

    for (int tt = 0; tt < 8; ++tt) {
        const int tap = tt >> 1;
        const int fh = (tt & 1) * 64;
        __syncthreads();   // previous tile's compute done (also covers xsT on tt=0)
        #pragma unroll
        for (int i = 0; i < 8; ++i) {
            int idx = tid + 256 * i;
            int j = idx >> 5, q = idx & 31;
            float4 v = *reinterpret_cast<const float4*>(
                w + (size_t)(fh + j) * 512 + tap * 128 + q * 4);
            wsT[(4 * q + 0) * XS_STRIDE + j] = v.x;
            wsT[(4 * q + 1) * XS_STRIDE + j] = v.y;
            wsT[(4 * q + 2) * XS_STRIDE + j] = v.z;
            wsT[(4 * q + 3) * XS_STRIDE + j] = v.w;
        }
        __syncthreads();

        float acc[4][4];
        #pragma unroll
        for (int a = 0; a < 4; ++a)
            #pragma unroll
            for (int b = 0; b < 4; ++b) acc[a][b] = 0.f;

        #pragma unroll 4
        for (int g = 0; g < 128; ++g) {
            float4 xv = *reinterpret_cast<const float4*>(xsT + g * XS_STRIDE + ni);
            float4 wv = *reinterpret_cast<const float4*>(wsT + g * XS_STRIDE + fj);
            const float xa[4] = {xv.x, xv.y, xv.z, xv.w};
            const float wa[4] = {wv.x, wv.y, wv.z, wv.w};
            #pragma unroll
            for (int a = 0; a < 4; ++a)
                #pragma unroll
                for (int b = 0; b < 4; ++b) acc[a][b] += xa[a] * wa[b];
        }

        #pragma unroll
        for (int b = 0; b < 4; ++b) {
            float4 o = make_float4(acc[0][b], acc[1][b], acc[2][b], acc[3][b]);
            *reinterpret_cast<float4*>(
                P + ((size_t)tap * FF + fh + fj + b) * NN + n0 + ni) = o;
        }
    }
}

// ---------------------------------------------------------------------------
// launch: prep, then 3 Horner GEMMs  y = ((P3 S + P2) S + P1) S + P0 + b
// ---------------------------------------------------------------------------
extern "C" void kernel_launch(void* const* d_in, const int* in_sizes, int n_in,
                              void* d_out, int out_size)
{
    (void)in_sizes; (void)n_in; (void)out_size;
    const float* x    = (const float*)d_in[0];
    const float* S    = (const float*)d_in[1];
    const float* w    = (const float*)d_in[2];
    const float* bias = (const float*)d_in[3];
    float* out = (float*)d_out;

    float *P, *v;
    cudaGetSymbolAddress((void**)&P, g_P);
    cudaGetSymbolAddress((void**)&v, g_v);
    float* P0 = P;
    float* P1 = P + (size_t)FF * NN;
    float* P2 = P + (size_t)2 * FF * NN;
    float* P3 = P + (size_t)3 * FF * NN;
    float* v0 = v;
    float* v1 = v + (size_t)FF * NN;

    cudaFuncSetAttribute(prep_reg, cudaFuncAttributeMaxDynamicSharedMemorySize, PREP_SMEM);
    cudaFuncSetAttribute(gemm_ws, cudaFuncAttributeMaxDynamicSharedMemorySize, GEMM_SMEM);

    prep_reg<<<NN / 64, 256, PREP_SMEM>>>(x, w, P);
    gemm_ws<<<NN / BN, 384, GEMM_SMEM>>>(P3, S, P2, nullptr, v0);
    gemm_ws<<<NN / BN, 384, GEMM_SMEM>>>(v0, S, P1, nullptr, v1);
    gemm_ws<<<NN / BN, 384, GEMM_SMEM>>>(v1, S, P0, bias, out);
}